// round 3
// baseline (speedup 1.0000x reference)
#include <cuda_runtime.h>
#include <cstdint>

// Problem constants (fixed by the dataset)
#define MAX_N 100000
#define D 128          // D_IN == D_OUT == 128
#define D4 (D/4)       // 32 float4 per row

// Scratch: y = x @ W  (51.2 MB, __device__ global to respect alloc rules)
__device__ float g_y[(size_t)MAX_N * D];

// ---------------------------------------------------------------------------
// Kernel 1: out[n, :] = b[:]
// ---------------------------------------------------------------------------
__global__ void init_out_kernel(float4* __restrict__ out4,
                                const float4* __restrict__ b4, int total4) {
    int i = blockIdx.x * blockDim.x + threadIdx.x;
    if (i < total4) {
        out4[i] = b4[i & (D4 - 1)];
    }
}

// ---------------------------------------------------------------------------
// Kernel 2: y = x @ W   (N x 128) @ (128 x 128)
// 128-row x 128-col tile per block, 256 threads, 8x8 accum per thread.
// Both x-tile and W live in (padded) shared memory.
// ---------------------------------------------------------------------------
#define GEMM_THREADS 256
#define TILE_M 128
#define ROWSTRIDE4 33            // 128 floats + 4 pad, in float4 units
#define ROWSTRIDE_F 132

__global__ void gemm_kernel(const float4* __restrict__ x4,
                            const float4* __restrict__ W4,
                            float* __restrict__ y, int N) {
    extern __shared__ float4 sm4[];
    float4* xs4 = sm4;                       // [128][33] float4
    float4* Ws4 = sm4 + TILE_M * ROWSTRIDE4; // [128][33] float4

    const int tid = threadIdx.x;
    const int row0 = blockIdx.x * TILE_M;

    // Cooperative load: 128 rows x 32 float4 each for x-tile and W.
    const float4 zero4 = make_float4(0.f, 0.f, 0.f, 0.f);
#pragma unroll
    for (int i = 0; i < 16; i++) {
        int idx = i * GEMM_THREADS + tid;    // 0 .. 4095
        int r = idx >> 5;                    // 0..127
        int c = idx & 31;                    // 0..31
        int grow = row0 + r;
        xs4[r * ROWSTRIDE4 + c] = (grow < N) ? x4[(size_t)grow * D4 + c] : zero4;
        Ws4[r * ROWSTRIDE4 + c] = W4[r * D4 + c];
    }
    __syncthreads();

    const int ty = tid >> 4;   // 0..15 -> rows ty*8 .. ty*8+7
    const int tx = tid & 15;   // 0..15 -> cols tx*8 .. tx*8+7

    float acc[8][8];
#pragma unroll
    for (int i = 0; i < 8; i++)
#pragma unroll
        for (int j = 0; j < 8; j++) acc[i][j] = 0.f;

    const float* xsf = reinterpret_cast<const float*>(xs4);

#pragma unroll 4
    for (int k = 0; k < D; k++) {
        float a[8];
#pragma unroll
        for (int i = 0; i < 8; i++)
            a[i] = xsf[(ty * 8 + i) * ROWSTRIDE_F + k];
        float4 b0 = Ws4[k * ROWSTRIDE4 + tx * 2];
        float4 b1 = Ws4[k * ROWSTRIDE4 + tx * 2 + 1];
        float bb[8] = {b0.x, b0.y, b0.z, b0.w, b1.x, b1.y, b1.z, b1.w};
#pragma unroll
        for (int i = 0; i < 8; i++)
#pragma unroll
            for (int j = 0; j < 8; j++)
                acc[i][j] = fmaf(a[i], bb[j], acc[i][j]);
    }

    // Write back 8x8 tile as two float4 per row.
#pragma unroll
    for (int i = 0; i < 8; i++) {
        int row = row0 + ty * 8 + i;
        if (row < N) {
            float4* yrow = reinterpret_cast<float4*>(y + (size_t)row * D + tx * 8);
            yrow[0] = make_float4(acc[i][0], acc[i][1], acc[i][2], acc[i][3]);
            yrow[1] = make_float4(acc[i][4], acc[i][5], acc[i][6], acc[i][7]);
        }
    }
}

// ---------------------------------------------------------------------------
// Kernel 3: for each edge e: out[dst[e], :] += y[src[e], :]
// One warp per edge; lane l handles floats [4l, 4l+4).
// edge_index is int32 (JAX x32 default downgrades int64 -> int32).
// ---------------------------------------------------------------------------
__global__ void scatter_kernel(const float* __restrict__ y,
                               const int* __restrict__ ei,
                               float* __restrict__ out, int E) {
    int e = (blockIdx.x * blockDim.x + threadIdx.x) >> 5;
    if (e >= E) return;
    int lane = threadIdx.x & 31;

    int src = ei[e];          // row 0 of edge_index
    int dst = ei[E + e];      // row 1

    const float4 v = *reinterpret_cast<const float4*>(y + (size_t)src * D + lane * 4);
    float* p = out + (size_t)dst * D + lane * 4;
    asm volatile("red.global.add.v4.f32 [%0], {%1, %2, %3, %4};"
                 :: "l"(p), "f"(v.x), "f"(v.y), "f"(v.z), "f"(v.w)
                 : "memory");
}

// ---------------------------------------------------------------------------
// Launch
// ---------------------------------------------------------------------------
extern "C" void kernel_launch(void* const* d_in, const int* in_sizes, int n_in,
                              void* d_out, int out_size) {
    const float* x = (const float*)d_in[0];
    const int* ei = (const int*)d_in[1];
    const float* W = (const float*)d_in[2];
    const float* b = (const float*)d_in[3];
    float* out = (float*)d_out;

    const int N = in_sizes[0] / D;
    const int E = in_sizes[1] / 2;

    float* y;
    cudaGetSymbolAddress((void**)&y, g_y);

    // 1) out = broadcast(b)
    {
        int total4 = N * D4;
        int threads = 256;
        int blocks = (total4 + threads - 1) / threads;
        init_out_kernel<<<blocks, threads>>>((float4*)out, (const float4*)b, total4);
    }

    // 2) y = x @ W
    {
        int smem = 2 * TILE_M * ROWSTRIDE4 * (int)sizeof(float4);  // 135168 B
        cudaFuncSetAttribute(gemm_kernel, cudaFuncAttributeMaxDynamicSharedMemorySize, smem);
        int blocks = (N + TILE_M - 1) / TILE_M;
        gemm_kernel<<<blocks, GEMM_THREADS, smem>>>((const float4*)x, (const float4*)W, y, N);
    }

    // 3) scatter-add: out[dst] += y[src]
    {
        int threads = 256;                      // 8 warps -> 8 edges per block
        int blocks = (E + 7) / 8;
        scatter_kernel<<<blocks, threads>>>(y, ei, out, E);
    }
}

// round 4
// speedup vs baseline: 2.2021x; 2.2021x over previous
#include <cuda_runtime.h>
#include <cstdint>

#define MAX_N 100000
#define MAX_E 1600000
#define D 128
#define D4 (D/4)

// ---------------------------------------------------------------------------
// Static scratch (alloc rules: __device__ globals only)
// ---------------------------------------------------------------------------
__device__ float g_agg[(size_t)MAX_N * D];     // segment_sum(x[src], dst)
__device__ int   g_deg[MAX_N];                  // per-dst degree (histogram)
__device__ int   g_pos[MAX_N];                  // fill cursors
__device__ int   g_off[MAX_N + 1];              // CSR offsets
__device__ int   g_part[256];                   // scan partials
__device__ int   g_srcs[MAX_E];                 // dst-bucketed src ids

// ---------------------------------------------------------------------------
// 1) histogram of dst
// ---------------------------------------------------------------------------
__global__ void hist_kernel(const int* __restrict__ ei, int* __restrict__ deg, int E) {
    int i = blockIdx.x * blockDim.x + threadIdx.x;
    if (i < E) atomicAdd(&deg[ei[E + i]], 1);
}

// ---------------------------------------------------------------------------
// 2) 3-phase exclusive scan over deg[0..N) -> off[0..N]
//    phase A: per-block (1024 elems) partial sums
// ---------------------------------------------------------------------------
#define SCAN_T 256
#define SCAN_ELEMS 1024   // 4 per thread

__global__ void scanA_kernel(const int* __restrict__ deg, int* __restrict__ part, int N) {
    __shared__ int s[SCAN_T];
    int base = blockIdx.x * SCAN_ELEMS + threadIdx.x * 4;
    int sum = 0;
#pragma unroll
    for (int i = 0; i < 4; i++) {
        int idx = base + i;
        if (idx < N) sum += deg[idx];
    }
    s[threadIdx.x] = sum;
    __syncthreads();
    for (int stride = SCAN_T / 2; stride > 0; stride >>= 1) {
        if (threadIdx.x < stride) s[threadIdx.x] += s[threadIdx.x + stride];
        __syncthreads();
    }
    if (threadIdx.x == 0) part[blockIdx.x] = s[0];
}

//    phase B: serial exclusive scan of partials (tiny), also writes off[N]=E
__global__ void scanB_kernel(int* __restrict__ part, int* __restrict__ off,
                             int nblocks, int N) {
    if (threadIdx.x == 0 && blockIdx.x == 0) {
        int run = 0;
        for (int i = 0; i < nblocks; i++) {
            int v = part[i];
            part[i] = run;
            run += v;
        }
        off[N] = run;   // == E
    }
}

//    phase C: per-block exclusive scan + base offset -> off[i]
__global__ void scanC_kernel(const int* __restrict__ deg, const int* __restrict__ part,
                             int* __restrict__ off, int N) {
    __shared__ int s[SCAN_T];
    int base = blockIdx.x * SCAN_ELEMS + threadIdx.x * 4;
    int v[4];
    int sum = 0;
#pragma unroll
    for (int i = 0; i < 4; i++) {
        int idx = base + i;
        v[i] = (idx < N) ? deg[idx] : 0;
        sum += v[i];
    }
    s[threadIdx.x] = sum;
    __syncthreads();
    // Hillis-Steele inclusive scan over per-thread sums
    for (int stride = 1; stride < SCAN_T; stride <<= 1) {
        int add = (threadIdx.x >= stride) ? s[threadIdx.x - stride] : 0;
        __syncthreads();
        s[threadIdx.x] += add;
        __syncthreads();
    }
    int excl = part[blockIdx.x] + s[threadIdx.x] - sum;  // exclusive prefix of this thread
#pragma unroll
    for (int i = 0; i < 4; i++) {
        int idx = base + i;
        if (idx < N) off[idx] = excl;
        excl += v[i];
    }
}

// ---------------------------------------------------------------------------
// 3) fill dst-buckets with src ids
// ---------------------------------------------------------------------------
__global__ void fill_kernel(const int* __restrict__ ei, const int* __restrict__ off,
                            int* __restrict__ pos, int* __restrict__ srcs, int E) {
    int i = blockIdx.x * blockDim.x + threadIdx.x;
    if (i < E) {
        int dst = ei[E + i];
        int p = atomicAdd(&pos[dst], 1);
        srcs[off[dst] + p] = ei[i];
    }
}

// ---------------------------------------------------------------------------
// 4) aggregate: agg[n,:] = sum over bucket n of x[src,:]   (warp per node)
// ---------------------------------------------------------------------------
__global__ void agg_kernel(const float4* __restrict__ x4,
                           const int* __restrict__ off, const int* __restrict__ srcs,
                           float4* __restrict__ agg4, int N) {
    int warp = (blockIdx.x * blockDim.x + threadIdx.x) >> 5;
    if (warp >= N) return;
    int lane = threadIdx.x & 31;

    int j = off[warp];
    int jend = off[warp + 1];

    float4 acc = make_float4(0.f, 0.f, 0.f, 0.f);
    // 2-way unrolled for MLP
    for (; j + 2 <= jend; j += 2) {
        int s0 = __ldg(&srcs[j]);
        int s1 = __ldg(&srcs[j + 1]);
        float4 v0 = __ldg(&x4[(size_t)s0 * D4 + lane]);
        float4 v1 = __ldg(&x4[(size_t)s1 * D4 + lane]);
        acc.x += v0.x + v1.x;
        acc.y += v0.y + v1.y;
        acc.z += v0.z + v1.z;
        acc.w += v0.w + v1.w;
    }
    if (j < jend) {
        int s0 = __ldg(&srcs[j]);
        float4 v0 = __ldg(&x4[(size_t)s0 * D4 + lane]);
        acc.x += v0.x; acc.y += v0.y; acc.z += v0.z; acc.w += v0.w;
    }
    agg4[(size_t)warp * D4 + lane] = acc;
}

// ---------------------------------------------------------------------------
// 5) GEMM + bias: out = agg @ W + b
// ---------------------------------------------------------------------------
#define GEMM_THREADS 256
#define TILE_M 128
#define ROWSTRIDE4 33
#define ROWSTRIDE_F 132

__global__ void gemm_bias_kernel(const float4* __restrict__ a4,
                                 const float4* __restrict__ W4,
                                 const float4* __restrict__ b4,
                                 float* __restrict__ out, int N) {
    extern __shared__ float4 sm4[];
    float4* xs4 = sm4;
    float4* Ws4 = sm4 + TILE_M * ROWSTRIDE4;

    const int tid = threadIdx.x;
    const int row0 = blockIdx.x * TILE_M;

    const float4 zero4 = make_float4(0.f, 0.f, 0.f, 0.f);
#pragma unroll
    for (int i = 0; i < 16; i++) {
        int idx = i * GEMM_THREADS + tid;
        int r = idx >> 5;
        int c = idx & 31;
        int grow = row0 + r;
        xs4[r * ROWSTRIDE4 + c] = (grow < N) ? a4[(size_t)grow * D4 + c] : zero4;
        Ws4[r * ROWSTRIDE4 + c] = W4[r * D4 + c];
    }
    __syncthreads();

    const int ty = tid >> 4;
    const int tx = tid & 15;

    float acc[8][8];
#pragma unroll
    for (int i = 0; i < 8; i++)
#pragma unroll
        for (int j = 0; j < 8; j++) acc[i][j] = 0.f;

    const float* xsf = reinterpret_cast<const float*>(xs4);

#pragma unroll 4
    for (int k = 0; k < D; k++) {
        float a[8];
#pragma unroll
        for (int i = 0; i < 8; i++)
            a[i] = xsf[(ty * 8 + i) * ROWSTRIDE_F + k];
        float4 w0 = Ws4[k * ROWSTRIDE4 + tx * 2];
        float4 w1 = Ws4[k * ROWSTRIDE4 + tx * 2 + 1];
        float ww[8] = {w0.x, w0.y, w0.z, w0.w, w1.x, w1.y, w1.z, w1.w};
#pragma unroll
        for (int i = 0; i < 8; i++)
#pragma unroll
            for (int j = 0; j < 8; j++)
                acc[i][j] = fmaf(a[i], ww[j], acc[i][j]);
    }

    // bias for this thread's 8 columns
    float4 bb0 = b4[tx * 2];
    float4 bb1 = b4[tx * 2 + 1];

#pragma unroll
    for (int i = 0; i < 8; i++) {
        int row = row0 + ty * 8 + i;
        if (row < N) {
            float4* orow = reinterpret_cast<float4*>(out + (size_t)row * D + tx * 8);
            orow[0] = make_float4(acc[i][0] + bb0.x, acc[i][1] + bb0.y,
                                  acc[i][2] + bb0.z, acc[i][3] + bb0.w);
            orow[1] = make_float4(acc[i][4] + bb1.x, acc[i][5] + bb1.y,
                                  acc[i][6] + bb1.z, acc[i][7] + bb1.w);
        }
    }
}

// ---------------------------------------------------------------------------
// Launch
// ---------------------------------------------------------------------------
extern "C" void kernel_launch(void* const* d_in, const int* in_sizes, int n_in,
                              void* d_out, int out_size) {
    const float* x = (const float*)d_in[0];
    const int* ei = (const int*)d_in[1];
    const float* W = (const float*)d_in[2];
    const float* b = (const float*)d_in[3];
    float* out = (float*)d_out;

    const int N = in_sizes[0] / D;
    const int E = in_sizes[1] / 2;

    float* agg;  int* deg;  int* pos;  int* off;  int* part;  int* srcs;
    cudaGetSymbolAddress((void**)&agg,  g_agg);
    cudaGetSymbolAddress((void**)&deg,  g_deg);
    cudaGetSymbolAddress((void**)&pos,  g_pos);
    cudaGetSymbolAddress((void**)&off,  g_off);
    cudaGetSymbolAddress((void**)&part, g_part);
    cudaGetSymbolAddress((void**)&srcs, g_srcs);

    // zero counters
    cudaMemsetAsync(deg, 0, N * sizeof(int));
    cudaMemsetAsync(pos, 0, N * sizeof(int));

    // 1) histogram
    {
        int threads = 256;
        hist_kernel<<<(E + threads - 1) / threads, threads>>>(ei, deg, E);
    }

    // 2) exclusive scan deg -> off
    int nblocks = (N + SCAN_ELEMS - 1) / SCAN_ELEMS;
    scanA_kernel<<<nblocks, SCAN_T>>>(deg, part, N);
    scanB_kernel<<<1, 32>>>(part, off, nblocks, N);
    scanC_kernel<<<nblocks, SCAN_T>>>(deg, part, off, N);

    // 3) fill buckets
    {
        int threads = 256;
        fill_kernel<<<(E + threads - 1) / threads, threads>>>(ei, off, pos, srcs, E);
    }

    // 4) aggregate (warp per node, 8 warps per block)
    {
        int threads = 256;
        int blocks = (N + 7) / 8;
        agg_kernel<<<blocks, threads>>>((const float4*)x, off, srcs, (float4*)agg, N);
    }

    // 5) out = agg @ W + b
    {
        int smem = 2 * TILE_M * ROWSTRIDE4 * (int)sizeof(float4);
        cudaFuncSetAttribute(gemm_bias_kernel, cudaFuncAttributeMaxDynamicSharedMemorySize, smem);
        int blocks = (N + TILE_M - 1) / TILE_M;
        gemm_bias_kernel<<<blocks, GEMM_THREADS, smem>>>(
            (const float4*)agg, (const float4*)W, (const float4*)b, out, N);
    }
}